// round 2
// baseline (speedup 1.0000x reference)
#include <cuda_runtime.h>

#define TT   512
#define BSZ  256
#define DIN  64
#define HH   128
#define G4   (4*HH)      // 512 gate rows per layer
#define K0   (DIN+HH)    // 192
#define K1   (2*HH)      // 256
#define BPC  4           // batch elements per CTA
#define NCTA (BSZ/BPC)   // 64
#define NTHR 512

// Transposed weights: W0T[k*G4 + g], W1T[k*G4 + g]  (coalesced per-warp loads)
__device__ float g_W0T[K0 * G4];
__device__ float g_W1T[K1 * G4];

__global__ void transpose_kernel(const float* __restrict__ Wih0,
                                 const float* __restrict__ Whh0,
                                 const float* __restrict__ Wih1,
                                 const float* __restrict__ Whh1)
{
    int idx = blockIdx.x * blockDim.x + threadIdx.x;
    int stride = gridDim.x * blockDim.x;
    for (int i = idx; i < K0 * G4; i += stride) {
        int k = i / G4, g = i % G4;
        g_W0T[i] = (k < DIN) ? Wih0[g * DIN + k] : Whh0[g * HH + (k - DIN)];
    }
    for (int i = idx; i < K1 * G4; i += stride) {
        int k = i / G4, g = i % G4;
        g_W1T[i] = (k < HH) ? Wih1[g * HH + k] : Whh1[g * HH + (k - HH)];
    }
}

__device__ __forceinline__ float sigf(float x) {
    return 1.0f / (1.0f + __expf(-x));
}

__global__ void __launch_bounds__(NTHR, 1)
lstm_kernel(const float* __restrict__ state,
            const float* __restrict__ b_ih0, const float* __restrict__ b_hh0,
            const float* __restrict__ b_ih1, const float* __restrict__ b_hh1,
            const float* __restrict__ W_out, const float* __restrict__ b_out,
            float* __restrict__ out)
{
    __shared__ float sxh0[BPC][K0];   // [x_t | h0_prev] per batch
    __shared__ float sxh1[BPC][K1];   // [h0_new | h1_prev] per batch
    __shared__ float sc0[BPC][HH];
    __shared__ float sc1[BPC][HH];
    __shared__ float sg[BPC][G4];     // gate pre-activations
    __shared__ float swout[HH];
    __shared__ float sred[16];        // per-warp head partials
    __shared__ float sbout;

    const int tid = threadIdx.x;
    const int b0  = blockIdx.x * BPC;
    const int g   = tid;              // gate row owned by this thread (512 == NTHR)

    if (tid < HH) swout[tid] = W_out[tid];
    if (tid == 0) sbout = b_out[0];
    for (int i = tid; i < BPC * HH; i += NTHR) {
        int bb = i / HH, j = i % HH;
        sc0[bb][j] = 0.0f;
        sc1[bb][j] = 0.0f;
        sxh0[bb][DIN + j] = 0.0f;     // h0 = 0
        sxh1[bb][j]       = 0.0f;
        sxh1[bb][HH + j]  = 0.0f;     // h1 = 0
    }
    const float bias0 = b_ih0[g] + b_hh0[g];
    const float bias1 = b_ih1[g] + b_hh1[g];
    __syncthreads();

    const int bb = tid >> 7;          // activation-phase mapping
    const int j  = tid & (HH - 1);

    for (int t = 0; t < TT; ++t) {
        // ---- A: load x_t for our 4 batch elements ----
        if (tid < BPC * DIN) {
            int lb = tid / DIN, k = tid % DIN;
            sxh0[lb][k] = state[(t * BSZ + b0 + lb) * DIN + k];
        }
        __syncthreads();  // S1

        // ---- B: layer0 gates: row g, dot length 192, 4 batch ----
        {
            float a0 = bias0, a1 = bias0, a2 = bias0, a3 = bias0;
            const float4* x0 = (const float4*)sxh0[0];
            const float4* x1 = (const float4*)sxh0[1];
            const float4* x2 = (const float4*)sxh0[2];
            const float4* x3 = (const float4*)sxh0[3];
            const float* wp = &g_W0T[g];
            #pragma unroll 4
            for (int k4 = 0; k4 < K0 / 4; ++k4) {
                float4 v0 = x0[k4], v1 = x1[k4], v2 = x2[k4], v3 = x3[k4];
                float w0 = __ldg(wp);           wp += G4;
                float w1 = __ldg(wp);           wp += G4;
                float w2 = __ldg(wp);           wp += G4;
                float w3 = __ldg(wp);           wp += G4;
                a0 += w0 * v0.x; a1 += w0 * v1.x; a2 += w0 * v2.x; a3 += w0 * v3.x;
                a0 += w1 * v0.y; a1 += w1 * v1.y; a2 += w1 * v2.y; a3 += w1 * v3.y;
                a0 += w2 * v0.z; a1 += w2 * v1.z; a2 += w2 * v2.z; a3 += w2 * v3.z;
                a0 += w3 * v0.w; a1 += w3 * v1.w; a2 += w3 * v2.w; a3 += w3 * v3.w;
            }
            sg[0][g] = a0; sg[1][g] = a1; sg[2][g] = a2; sg[3][g] = a3;
        }
        __syncthreads();  // S2

        // ---- C: layer0 activations ----
        {
            float gi = sigf (sg[bb][j]);
            float gf = sigf (sg[bb][HH + j]);
            float gg = tanhf(sg[bb][2 * HH + j]);
            float go = sigf (sg[bb][3 * HH + j]);
            float c  = gf * sc0[bb][j] + gi * gg;
            sc0[bb][j] = c;
            float h = go * tanhf(c);
            sxh0[bb][DIN + j] = h;    // recurrent input, next step
            sxh1[bb][j]       = h;    // feeds layer1 now
        }
        __syncthreads();  // S3

        // ---- D: layer1 gates: row g, dot length 256, 4 batch ----
        {
            float a0 = bias1, a1 = bias1, a2 = bias1, a3 = bias1;
            const float4* x0 = (const float4*)sxh1[0];
            const float4* x1 = (const float4*)sxh1[1];
            const float4* x2 = (const float4*)sxh1[2];
            const float4* x3 = (const float4*)sxh1[3];
            const float* wp = &g_W1T[g];
            #pragma unroll 4
            for (int k4 = 0; k4 < K1 / 4; ++k4) {
                float4 v0 = x0[k4], v1 = x1[k4], v2 = x2[k4], v3 = x3[k4];
                float w0 = __ldg(wp);           wp += G4;
                float w1 = __ldg(wp);           wp += G4;
                float w2 = __ldg(wp);           wp += G4;
                float w3 = __ldg(wp);           wp += G4;
                a0 += w0 * v0.x; a1 += w0 * v1.x; a2 += w0 * v2.x; a3 += w0 * v3.x;
                a0 += w1 * v0.y; a1 += w1 * v1.y; a2 += w1 * v2.y; a3 += w1 * v3.y;
                a0 += w2 * v0.z; a1 += w2 * v1.z; a2 += w2 * v2.z; a3 += w2 * v3.z;
                a0 += w3 * v0.w; a1 += w3 * v1.w; a2 += w3 * v2.w; a3 += w3 * v3.w;
            }
            sg[0][g] = a0; sg[1][g] = a1; sg[2][g] = a2; sg[3][g] = a3;
        }
        __syncthreads();  // S4

        // ---- E: layer1 activations + head partial dot ----
        {
            float gi = sigf (sg[bb][j]);
            float gf = sigf (sg[bb][HH + j]);
            float gg = tanhf(sg[bb][2 * HH + j]);
            float go = sigf (sg[bb][3 * HH + j]);
            float c  = gf * sc1[bb][j] + gi * gg;
            sc1[bb][j] = c;
            float h = go * tanhf(c);
            sxh1[bb][HH + j] = h;     // recurrent input, next step
            float p = h * swout[j];
            #pragma unroll
            for (int off = 16; off; off >>= 1)
                p += __shfl_down_sync(0xffffffffu, p, off);
            if ((tid & 31) == 0) sred[tid >> 5] = p;
        }
        __syncthreads();  // S5

        // ---- F: finalize head output (4 warps per batch element) ----
        if (tid < BPC) {
            float v = sred[4 * tid] + sred[4 * tid + 1]
                    + sred[4 * tid + 2] + sred[4 * tid + 3] + sbout;
            out[t * BSZ + b0 + tid] = v;
        }
        // no sync needed: sred isn't rewritten until after S4 of next iter
    }
}

extern "C" void kernel_launch(void* const* d_in, const int* in_sizes, int n_in,
                              void* d_out, int out_size)
{
    const float* state = (const float*)d_in[0];
    const float* W_ih0 = (const float*)d_in[1];
    const float* W_hh0 = (const float*)d_in[2];
    const float* b_ih0 = (const float*)d_in[3];
    const float* b_hh0 = (const float*)d_in[4];
    const float* W_ih1 = (const float*)d_in[5];
    const float* W_hh1 = (const float*)d_in[6];
    const float* b_ih1 = (const float*)d_in[7];
    const float* b_hh1 = (const float*)d_in[8];
    const float* W_out = (const float*)d_in[9];
    const float* b_out = (const float*)d_in[10];
    float* out = (float*)d_out;

    transpose_kernel<<<224, 512>>>(W_ih0, W_hh0, W_ih1, W_hh1);
    lstm_kernel<<<NCTA, NTHR>>>(state, b_ih0, b_hh0, b_ih1, b_hh1,
                                W_out, b_out, out);
}